// round 3
// baseline (speedup 1.0000x reference)
#include <cuda_runtime.h>
#include <math.h>

// theta [B=4] degrees, image [C=3, H=80, W=80] -> out [B, C, H, W].
// Reference's dense [B,N,N] tent-weight matmul == bilinear gather with
// zero weight for out-of-grid taps (tent support <= 2 integer taps/axis).
//
// One thread per OUTPUT ELEMENT (b,c,y,x): 76800 threads = 600 CTAs x 128.
// Maximizes SM coverage (all 148 SMs, ~4 CTAs each) and cross-CTA latency
// overlap; per-thread body is just 4 LDG + 1 STG.

#define B_ 4
#define C_ 3
#define H_ 80
#define W_ 80
#define HW_ (H_ * W_)

__global__ __launch_bounds__(128) void rot_bilinear_kernel(
    const float* __restrict__ theta,   // [B]
    const float* __restrict__ image,   // [C, H, W]
    float* __restrict__ out)           // [B, C, H, W]
{
    // grid sized exactly: 600 * 128 == 4*3*80*80 == 76800, no guard.
    const int t = blockIdx.x * blockDim.x + threadIdx.x;

    const int x = t % W_;
    const int y = (t / W_) % H_;
    const int c = (t / HW_) % C_;
    const int b = t / (C_ * HW_);

    const float cx = (W_ - 1) * 0.5f;
    const float cy = (H_ - 1) * 0.5f;

    const float th = __ldg(theta + b) * 0.017453292519943295f;  // deg2rad
    float sn, cs;
    __sincosf(th, &sn, &cs);

    const float x_rel = (float)x - cx;
    const float y_rel = (float)y - cy;

    const float sx = fmaf(cs, x_rel, fmaf(sn, y_rel, cx));    //  cos*x + sin*y + cx
    const float sy = fmaf(-sn, x_rel, fmaf(cs, y_rel, cy));   // -sin*x + cos*y + cy

    const int ix0 = __float2int_rd(sx);
    const int iy0 = __float2int_rd(sy);
    const int ix1 = ix0 + 1;
    const int iy1 = iy0 + 1;
    const float ax = sx - __int2float_rn(ix0);   // weight of ix1
    const float ay = sy - __int2float_rn(iy0);   // weight of iy1

    float wx0 = 1.0f - ax, wx1 = ax;
    float wy0 = 1.0f - ay, wy1 = ay;
    // zero weights for out-of-grid taps (matches reference truncated tent sum)
    if (ix0 < 0 || ix0 >= W_) wx0 = 0.0f;
    if (ix1 < 0 || ix1 >= W_) wx1 = 0.0f;
    if (iy0 < 0 || iy0 >= H_) wy0 = 0.0f;
    if (iy1 < 0 || iy1 >= H_) wy1 = 0.0f;

    // clamp indices so loads stay in-bounds (weight already zeroed)
    const int jx0 = min(max(ix0, 0), W_ - 1);
    const int jx1 = min(max(ix1, 0), W_ - 1);
    const int jy0 = min(max(iy0, 0), H_ - 1);
    const int jy1 = min(max(iy1, 0), H_ - 1);

    const float w00 = wy0 * wx0;
    const float w01 = wy0 * wx1;
    const float w10 = wy1 * wx0;
    const float w11 = wy1 * wx1;

    const float* img = image + c * HW_;
    const int r0 = jy0 * W_;
    const int r1 = jy1 * W_;

    float v = w00 * __ldg(img + r0 + jx0);
    v = fmaf(w01, __ldg(img + r0 + jx1), v);
    v = fmaf(w10, __ldg(img + r1 + jx0), v);
    v = fmaf(w11, __ldg(img + r1 + jx1), v);

    out[t] = v;   // flat (b,c,y,x) == thread index: fully coalesced
}

extern "C" void kernel_launch(void* const* d_in, const int* in_sizes, int n_in,
                              void* d_out, int out_size) {
    const float* theta = (const float*)d_in[0];   // [4]
    const float* image = (const float*)d_in[1];   // [3, 80, 80]
    float* out = (float*)d_out;                   // [4, 3, 80, 80]

    rot_bilinear_kernel<<<600, 128>>>(theta, image, out);  // exactly 76800 threads
}

// round 4
// speedup vs baseline: 1.0437x; 1.0437x over previous
#include <cuda_runtime.h>
#include <math.h>

// theta [B=4] degrees, image [C=3, H=80, W=80] -> out [B, C, H, W].
// Reference's dense [B,N,N] tent-weight matmul == bilinear gather with zero
// weight for out-of-grid taps (tent support <= 2 integer taps per axis).
//
// Latency-floor tuning: 4 output pixels per thread (float4 store), 19200
// threads = 600 warps in 120 CTAs (single wave, all-SM coverage), no integer
// div/mod in the thread path, 16 LDGs batched for one L2 round of exposure.

#define B_ 4
#define C_ 3
#define H_ 80
#define W_ 80
#define HW_ (H_ * W_)

__global__ __launch_bounds__(160) void rot_bilinear_kernel(
    const float* __restrict__ theta,   // [B]
    const float* __restrict__ image,   // [C, H, W]
    float* __restrict__ out)           // [B, C, H, W]
{
    // grid = (12, 10), block = (20, 8)
    // plane = blockIdx.x in [0,12): b = plane/3, c = plane%3   (uniform)
    // y = blockIdx.y*8 + threadIdx.y in [0,80)
    // x4 = threadIdx.x*4 : this thread covers x4..x4+3
    const int plane = blockIdx.x;
    const int b = plane / 3;          // uniform-pipe, cheap
    const int y = blockIdx.y * 8 + threadIdx.y;
    const int x4 = threadIdx.x * 4;

    const float cx = (W_ - 1) * 0.5f;
    const float cy = (H_ - 1) * 0.5f;

    const float th = __ldg(theta + b) * 0.017453292519943295f;  // deg2rad
    float sn, cs;
    __sincosf(th, &sn, &cs);

    const float x_rel = (float)x4 - cx;
    const float y_rel = (float)y - cy;

    // src coords for pixel x4; stepping +1 in x adds (cs, -sn)
    float sx = fmaf(cs, x_rel, fmaf(sn, y_rel, cx));
    float sy = fmaf(-sn, x_rel, fmaf(cs, y_rel, cy));

    const float* img = image + (plane % 3) * HW_;

    float res[4];
    float vx[4], vy[4];           // src coords per pixel
    #pragma unroll
    for (int i = 0; i < 4; i++) {
        vx[i] = sx; vy[i] = sy;
        sx += cs; sy -= sn;
    }

    // Per-pixel taps: compute all addresses/weights, batch all 16 loads.
    float w00[4], w01[4], w10[4], w11[4];
    int o00[4], o01[4], o10[4], o11[4];
    #pragma unroll
    for (int i = 0; i < 4; i++) {
        const int ix0 = __float2int_rd(vx[i]);
        const int iy0 = __float2int_rd(vy[i]);
        const int ix1 = ix0 + 1;
        const int iy1 = iy0 + 1;
        const float ax = vx[i] - __int2float_rn(ix0);
        const float ay = vy[i] - __int2float_rn(iy0);

        float wx0 = 1.0f - ax, wx1 = ax;
        float wy0 = 1.0f - ay, wy1 = ay;
        if (ix0 < 0 || ix0 >= W_) wx0 = 0.0f;
        if (ix1 < 0 || ix1 >= W_) wx1 = 0.0f;
        if (iy0 < 0 || iy0 >= H_) wy0 = 0.0f;
        if (iy1 < 0 || iy1 >= H_) wy1 = 0.0f;

        const int jx0 = min(max(ix0, 0), W_ - 1);
        const int jx1 = min(max(ix1, 0), W_ - 1);
        const int r0 = min(max(iy0, 0), H_ - 1) * W_;
        const int r1 = min(max(iy1, 0), H_ - 1) * W_;

        w00[i] = wy0 * wx0;  w01[i] = wy0 * wx1;
        w10[i] = wy1 * wx0;  w11[i] = wy1 * wx1;
        o00[i] = r0 + jx0;   o01[i] = r0 + jx1;
        o10[i] = r1 + jx0;   o11[i] = r1 + jx1;
    }

    float t00[4], t01[4], t10[4], t11[4];
    #pragma unroll
    for (int i = 0; i < 4; i++) {
        t00[i] = __ldg(img + o00[i]);
        t01[i] = __ldg(img + o01[i]);
        t10[i] = __ldg(img + o10[i]);
        t11[i] = __ldg(img + o11[i]);
    }

    #pragma unroll
    for (int i = 0; i < 4; i++) {
        float v = w00[i] * t00[i];
        v = fmaf(w01[i], t01[i], v);
        v = fmaf(w10[i], t10[i], v);
        res[i] = fmaf(w11[i], t11[i], v);
    }

    float4* dst = (float4*)(out + plane * HW_ + y * W_ + x4);
    *dst = make_float4(res[0], res[1], res[2], res[3]);
}

extern "C" void kernel_launch(void* const* d_in, const int* in_sizes, int n_in,
                              void* d_out, int out_size) {
    const float* theta = (const float*)d_in[0];   // [4]
    const float* image = (const float*)d_in[1];   // [3, 80, 80]
    float* out = (float*)d_out;                   // [4, 3, 80, 80]

    dim3 grid(12, 10);     // planes (b*3+c), y-groups of 8
    dim3 block(20, 8);     // x-groups of 4 px, y within group  -> 160 thr
    rot_bilinear_kernel<<<grid, block>>>(theta, image, out);   // 19200 threads
}